// round 4
// baseline (speedup 1.0000x reference)
#include <cuda_runtime.h>
#include <cstdint>

#define BB   8
#define SS   2048
#define EE   256
#define HH   4
#define HD   64
#define BHN  (BB*HH)           // 32
#define LB   16
#define XSZ  (BB*SS*EE)        // 4,194,304
#define QSZ  (BHN*SS*HD)       // 4,194,304

// ---------------- scratch (static device globals; no allocation) ----------------
__device__ __align__(16) float g_X[XSZ];                       // 16 MB (residual stream, in-place)
__device__ __align__(16) float g_Q[QSZ];                       // 16 MB
__device__ __align__(16) float g_K[QSZ];                       // 16 MB
__device__ __align__(16) float g_V[QSZ];                       // 16 MB
__device__ __align__(16) float g_Z[XSZ];                       // 16 MB (Zall layout [b,s,h,d])
__device__ __align__(16) float g_SC[(size_t)BHN*SS*SS];        // 512 MB scores / attention
__device__ __align__(16) float g_cmax[BHN*SS];
__device__ __align__(16) float g_rcs[BHN*SS];
__device__ __align__(16) float g_pmax[4*BHN*SS];
__device__ __align__(16) float g_psum[4*BHN*SS];
__device__ __align__(16) float g_part[BB*LB*8];

// ---------------- FFMA-only exp (avoids MUFU bottleneck: rt_SMSP=8) ----------------
__device__ __forceinline__ float fexp(float x) {
    x = fmaxf(fminf(x, 87.0f), -87.0f);
    float z = x * 1.4426950408889634f;          // x * log2(e)
    int   n = __float2int_rn(z);
    float f = z - (float)n;                     // f in [-0.5, 0.5]
    float t = f * 0.6931471805599453f;          // back to e-domain, |t| <= 0.347
    float p = 1.98412698412e-4f;                // 1/5040
    p = fmaf(p, t, 1.38888888889e-3f);          // 1/720
    p = fmaf(p, t, 8.33333333333e-3f);          // 1/120
    p = fmaf(p, t, 4.16666666667e-2f);          // 1/24
    p = fmaf(p, t, 1.66666666667e-1f);          // 1/6
    p = fmaf(p, t, 0.5f);
    p = fmaf(p, t, 1.0f);
    p = fmaf(p, t, 1.0f);
    return p * __int_as_float((n + 127) << 23);
}

// ---------------- embedding gather ----------------
__global__ void embed_kernel(const int* __restrict__ seqs, const float* __restrict__ emb) {
    int bs   = blockIdx.x * 4 + (threadIdx.x >> 6);
    int lane = threadIdx.x & 63;
    int tok  = seqs[bs];
    reinterpret_cast<float4*>(g_X)[(size_t)bs * 64 + lane] =
        reinterpret_cast<const float4*>(emb)[(size_t)tok * 64 + lane];
}

// ---------------- projection / ZF GEMM: C[m,n] = sum_k A[m,k]*W[n,k] ----------------
// M=16384, N=256 (grid.y*64), K=256. Tile 128x64, Kc=32, thread tile 8x4.
// MODE 0: A=g_X, epilogue relu(+bias), scatter to Q/K/V layout [bh,s,d]
// MODE 1: A=g_Z, epilogue += bias + residual into g_X (in place; element-local)
template<int MODE>
__global__ void __launch_bounds__(256)
proj_kernel(const float* __restrict__ W, const float* __restrict__ bias, int osel) {
    __shared__ float As[32][132];   // [k][m]
    __shared__ float Bs[32][68];    // [k][n]
    int tid = threadIdx.x;
    int tx = tid & 15, ty = tid >> 4;
    int m0 = blockIdx.x * 128, n0 = blockIdx.y * 64;
    const float* A = (MODE == 0) ? g_X : g_Z;

    float acc[8][4] = {};
    for (int kc = 0; kc < 256; kc += 32) {
        #pragma unroll
        for (int i = 0; i < 4; i++) {
            int idx = tid + i * 256;
            int row = idx >> 3, c4 = (idx & 7) * 4;
            float4 a = *reinterpret_cast<const float4*>(A + (size_t)(m0 + row) * 256 + kc + c4);
            As[c4 + 0][row] = a.x; As[c4 + 1][row] = a.y;
            As[c4 + 2][row] = a.z; As[c4 + 3][row] = a.w;
        }
        #pragma unroll
        for (int i = 0; i < 2; i++) {
            int idx = tid + i * 256;
            int row = idx >> 3, c4 = (idx & 7) * 4;
            float4 w = *reinterpret_cast<const float4*>(W + (size_t)(n0 + row) * 256 + kc + c4);
            Bs[c4 + 0][row] = w.x; Bs[c4 + 1][row] = w.y;
            Bs[c4 + 2][row] = w.z; Bs[c4 + 3][row] = w.w;
        }
        __syncthreads();
        #pragma unroll 8
        for (int kk = 0; kk < 32; kk++) {
            float4 a0 = *reinterpret_cast<float4*>(&As[kk][ty * 8]);
            float4 a1 = *reinterpret_cast<float4*>(&As[kk][ty * 8 + 4]);
            float4 b  = *reinterpret_cast<float4*>(&Bs[kk][tx * 4]);
            float av[8] = {a0.x, a0.y, a0.z, a0.w, a1.x, a1.y, a1.z, a1.w};
            float bv[4] = {b.x, b.y, b.z, b.w};
            #pragma unroll
            for (int i = 0; i < 8; i++)
                #pragma unroll
                for (int j = 0; j < 4; j++)
                    acc[i][j] = fmaf(av[i], bv[j], acc[i][j]);
        }
        __syncthreads();
    }

    float4 bb = *reinterpret_cast<const float4*>(bias + n0 + tx * 4);
    if (MODE == 0) {
        float* outp = (osel == 0) ? g_Q : (osel == 1 ? g_K : g_V);
        int h = n0 >> 6;
        #pragma unroll
        for (int i = 0; i < 8; i++) {
            int m = m0 + ty * 8 + i;
            int b = m >> 11, s = m & 2047;
            float4 v;
            v.x = fmaxf(acc[i][0] + bb.x, 0.f);
            v.y = fmaxf(acc[i][1] + bb.y, 0.f);
            v.z = fmaxf(acc[i][2] + bb.z, 0.f);
            v.w = fmaxf(acc[i][3] + bb.w, 0.f);
            *reinterpret_cast<float4*>(&outp[((size_t)(b * HH + h) * SS + s) * HD + tx * 4]) = v;
        }
    } else {
        #pragma unroll
        for (int i = 0; i < 8; i++) {
            int m = m0 + ty * 8 + i;
            float* dst = &g_X[(size_t)m * 256 + n0 + tx * 4];
            float4 o = *reinterpret_cast<float4*>(dst);
            o.x += acc[i][0] + bb.x; o.y += acc[i][1] + bb.y;
            o.z += acc[i][2] + bb.z; o.w += acc[i][3] + bb.w;
            *reinterpret_cast<float4*>(dst) = o;
        }
    }
}

// ---------------- QK^T / 16: per (b,h) 2048x2048x64; tile 128x128, 8x8/thread ----------------
__global__ void __launch_bounds__(256)
qk_kernel() {
    __shared__ float Qs[32][132];   // [k][s]
    __shared__ float Ks[32][132];   // [k][t]
    int tid = threadIdx.x;
    int tx = tid & 15, ty = tid >> 4;
    int s0 = blockIdx.x * 128, t0 = blockIdx.y * 128, bh = blockIdx.z;
    const float* Qp = g_Q + (size_t)bh * SS * HD;
    const float* Kp = g_K + (size_t)bh * SS * HD;

    float acc[8][8] = {};
    for (int kc = 0; kc < 64; kc += 32) {
        #pragma unroll
        for (int i = 0; i < 4; i++) {
            int idx = tid + i * 256;
            int row = idx >> 3, c4 = (idx & 7) * 4;
            float4 q = *reinterpret_cast<const float4*>(Qp + (size_t)(s0 + row) * HD + kc + c4);
            float4 k = *reinterpret_cast<const float4*>(Kp + (size_t)(t0 + row) * HD + kc + c4);
            Qs[c4 + 0][row] = q.x; Qs[c4 + 1][row] = q.y;
            Qs[c4 + 2][row] = q.z; Qs[c4 + 3][row] = q.w;
            Ks[c4 + 0][row] = k.x; Ks[c4 + 1][row] = k.y;
            Ks[c4 + 2][row] = k.z; Ks[c4 + 3][row] = k.w;
        }
        __syncthreads();
        #pragma unroll 4
        for (int kk = 0; kk < 32; kk++) {
            float4 a0 = *reinterpret_cast<float4*>(&Qs[kk][ty * 8]);
            float4 a1 = *reinterpret_cast<float4*>(&Qs[kk][ty * 8 + 4]);
            float4 b0 = *reinterpret_cast<float4*>(&Ks[kk][tx * 8]);
            float4 b1 = *reinterpret_cast<float4*>(&Ks[kk][tx * 8 + 4]);
            float av[8] = {a0.x, a0.y, a0.z, a0.w, a1.x, a1.y, a1.z, a1.w};
            float bv[8] = {b0.x, b0.y, b0.z, b0.w, b1.x, b1.y, b1.z, b1.w};
            #pragma unroll
            for (int i = 0; i < 8; i++)
                #pragma unroll
                for (int j = 0; j < 8; j++)
                    acc[i][j] = fmaf(av[i], bv[j], acc[i][j]);
        }
        __syncthreads();
    }
    const float sc = 0.0625f;  // 1/sqrt(EMBED) = 1/16
    #pragma unroll
    for (int i = 0; i < 8; i++) {
        size_t base = ((size_t)bh * SS + (s0 + ty * 8 + i)) * SS + t0 + tx * 8;
        float4 w0, w1;
        w0.x = acc[i][0]*sc; w0.y = acc[i][1]*sc; w0.z = acc[i][2]*sc; w0.w = acc[i][3]*sc;
        w1.x = acc[i][4]*sc; w1.y = acc[i][5]*sc; w1.z = acc[i][6]*sc; w1.w = acc[i][7]*sc;
        *reinterpret_cast<float4*>(g_SC + base)     = w0;
        *reinterpret_cast<float4*>(g_SC + base + 4) = w1;
    }
}

// ---------------- softmax over query axis: column stats, split over s for occupancy ----------------
__global__ void colstats1_kernel() {
    int bh = blockIdx.y, seg = blockIdx.z;
    int t = blockIdx.x * 256 + threadIdx.x;
    const float* p = g_SC + (size_t)bh * SS * SS + (size_t)seg * 512 * SS + t;
    float m = -3.0e38f, s = 0.f;
    #pragma unroll 4
    for (int i = 0; i < 512; i++) {
        float v = p[(size_t)i * SS];
        if (v <= m) s += fexp(v - m);
        else        { s = fmaf(s, fexp(m - v), 1.0f); m = v; }
    }
    g_pmax[(size_t)(seg * BHN + bh) * SS + t] = m;
    g_psum[(size_t)(seg * BHN + bh) * SS + t] = s;
}

__global__ void colstats2_kernel() {
    int bh = blockIdx.y;
    int t = blockIdx.x * 256 + threadIdx.x;
    float m = -3.0e38f, s = 0.f;
    #pragma unroll
    for (int seg = 0; seg < 4; seg++) {
        float mi = g_pmax[(size_t)(seg * BHN + bh) * SS + t];
        float si = g_psum[(size_t)(seg * BHN + bh) * SS + t];
        if (mi <= m) s += si * fexp(mi - m);
        else         { s = fmaf(s, fexp(m - mi), si); m = mi; }
    }
    g_cmax[bh * SS + t] = m;
    g_rcs [bh * SS + t] = 1.0f / s;
}

// ---------------- per-row: A1 = exp(S - cmax)*rcs ; A2 = softmax over t of A1 (in place) ----------------
__global__ void __launch_bounds__(256)
rownorm_kernel() {
    int bh = blockIdx.y, s = blockIdx.x;
    float* row = g_SC + ((size_t)bh * SS + s) * SS;
    int t = threadIdx.x * 8;

    float4 x0 = *reinterpret_cast<float4*>(row + t);
    float4 x1 = *reinterpret_cast<float4*>(row + t + 4);
    float4 cm0 = *reinterpret_cast<const float4*>(g_cmax + bh * SS + t);
    float4 cm1 = *reinterpret_cast<const float4*>(g_cmax + bh * SS + t + 4);
    float4 rc0 = *reinterpret_cast<const float4*>(g_rcs  + bh * SS + t);
    float4 rc1 = *reinterpret_cast<const float4*>(g_rcs  + bh * SS + t + 4);

    float v[8];
    v[0] = fexp(fexp(x0.x - cm0.x) * rc0.x);
    v[1] = fexp(fexp(x0.y - cm0.y) * rc0.y);
    v[2] = fexp(fexp(x0.z - cm0.z) * rc0.z);
    v[3] = fexp(fexp(x0.w - cm0.w) * rc0.w);
    v[4] = fexp(fexp(x1.x - cm1.x) * rc1.x);
    v[5] = fexp(fexp(x1.y - cm1.y) * rc1.y);
    v[6] = fexp(fexp(x1.z - cm1.z) * rc1.z);
    v[7] = fexp(fexp(x1.w - cm1.w) * rc1.w);

    float loc = ((v[0]+v[1])+(v[2]+v[3])) + ((v[4]+v[5])+(v[6]+v[7]));
    #pragma unroll
    for (int o = 16; o; o >>= 1) loc += __shfl_xor_sync(0xffffffffu, loc, o);
    __shared__ float red[9];
    if ((threadIdx.x & 31) == 0) red[threadIdx.x >> 5] = loc;
    __syncthreads();
    if (threadIdx.x == 0) {
        float tt = ((red[0]+red[1])+(red[2]+red[3])) + ((red[4]+red[5])+(red[6]+red[7]));
        red[8] = 1.0f / tt;
    }
    __syncthreads();
    float r = red[8];

    x0.x = v[0]*r; x0.y = v[1]*r; x0.z = v[2]*r; x0.w = v[3]*r;
    x1.x = v[4]*r; x1.y = v[5]*r; x1.z = v[6]*r; x1.w = v[7]*r;
    *reinterpret_cast<float4*>(row + t)     = x0;
    *reinterpret_cast<float4*>(row + t + 4) = x1;
}

// ---------------- Z = A2 @ V: per (b,h) 2048x64x2048; tile 128x64, Kc=32, 8x4/thread ----------------
__global__ void __launch_bounds__(256)
av_kernel() {
    __shared__ float As[32][132];   // [t][s]
    __shared__ float Vs[32][68];    // [t][d]
    int tid = threadIdx.x;
    int tx = tid & 15, ty = tid >> 4;
    int s0 = blockIdx.x * 128, bh = blockIdx.y;
    const float* Ap = g_SC + (size_t)bh * SS * SS;
    const float* Vp = g_V + (size_t)bh * SS * HD;

    float acc[8][4] = {};
    for (int tc = 0; tc < SS; tc += 32) {
        #pragma unroll
        for (int i = 0; i < 4; i++) {
            int idx = tid + i * 256;
            int row = idx >> 3, c4 = (idx & 7) * 4;
            float4 a = *reinterpret_cast<const float4*>(Ap + (size_t)(s0 + row) * SS + tc + c4);
            As[c4 + 0][row] = a.x; As[c4 + 1][row] = a.y;
            As[c4 + 2][row] = a.z; As[c4 + 3][row] = a.w;
        }
        #pragma unroll
        for (int i = 0; i < 2; i++) {
            int idx = tid + i * 256;
            int r = idx >> 4, c4 = (idx & 15) * 4;
            *reinterpret_cast<float4*>(&Vs[r][c4]) =
                *reinterpret_cast<const float4*>(Vp + (size_t)(tc + r) * HD + c4);
        }
        __syncthreads();
        #pragma unroll 8
        for (int kk = 0; kk < 32; kk++) {
            float4 a0 = *reinterpret_cast<float4*>(&As[kk][ty * 8]);
            float4 a1 = *reinterpret_cast<float4*>(&As[kk][ty * 8 + 4]);
            float4 b  = *reinterpret_cast<float4*>(&Vs[kk][tx * 4]);
            float av[8] = {a0.x, a0.y, a0.z, a0.w, a1.x, a1.y, a1.z, a1.w};
            float bv[4] = {b.x, b.y, b.z, b.w};
            #pragma unroll
            for (int i = 0; i < 8; i++)
                #pragma unroll
                for (int j = 0; j < 4; j++)
                    acc[i][j] = fmaf(av[i], bv[j], acc[i][j]);
        }
        __syncthreads();
    }
    int b = bh >> 2, h = bh & 3;
    #pragma unroll
    for (int i = 0; i < 8; i++) {
        int s = s0 + ty * 8 + i;
        float4 v;
        v.x = acc[i][0]; v.y = acc[i][1]; v.z = acc[i][2]; v.w = acc[i][3];
        *reinterpret_cast<float4*>(&g_Z[((size_t)(b * SS + s)) * 256 + h * HD + tx * 4]) = v;
    }
}

// ---------------- final classifier: y[b,l] = sigmoid(X[b,:].Wo[l,:] + bo[l]) ----------------
__global__ void __launch_bounds__(256)
outpartial_kernel(const float* __restrict__ Wo) {
    int bl = blockIdx.y;            // b*16 + l
    int sp = blockIdx.x;            // split 0..7
    int l = bl & 15, b = bl >> 4;
    const float4* wp = reinterpret_cast<const float4*>(Wo + (size_t)l * (SS * EE)) + (size_t)sp * 16384;
    const float4* xp = reinterpret_cast<const float4*>(g_X + (size_t)b * (SS * EE)) + (size_t)sp * 16384;
    float s = 0.f;
    #pragma unroll 4
    for (int i = 0; i < 64; i++) {
        int idx = threadIdx.x + i * 256;
        float4 w = wp[idx], x = xp[idx];
        s = fmaf(w.x, x.x, fmaf(w.y, x.y, fmaf(w.z, x.z, fmaf(w.w, x.w, s))));
    }
    #pragma unroll
    for (int o = 16; o; o >>= 1) s += __shfl_xor_sync(0xffffffffu, s, o);
    __shared__ float red[8];
    if ((threadIdx.x & 31) == 0) red[threadIdx.x >> 5] = s;
    __syncthreads();
    if (threadIdx.x == 0) {
        float tt = ((red[0]+red[1])+(red[2]+red[3])) + ((red[4]+red[5])+(red[6]+red[7]));
        g_part[bl * 8 + sp] = tt;
    }
}

__global__ void outfinal_kernel(const float* __restrict__ bo, float* __restrict__ out) {
    int bl = threadIdx.x;  // 0..127
    float s = bo[bl & 15];
    #pragma unroll
    for (int i = 0; i < 8; i++) s += g_part[bl * 8 + i];
    out[bl] = 1.0f / (1.0f + fexp(-s));
}

// ---------------- launch ----------------
extern "C" void kernel_launch(void* const* d_in, const int* in_sizes, int n_in,
                              void* d_out, int out_size) {
    const int*   seqs = (const int*)  d_in[0];
    const float* emb  = (const float*)d_in[1];
    const float* Wq   = (const float*)d_in[2];
    const float* bq   = (const float*)d_in[3];
    const float* Wk   = (const float*)d_in[4];
    const float* bk   = (const float*)d_in[5];
    const float* Wv   = (const float*)d_in[6];
    const float* bv   = (const float*)d_in[7];
    const float* Wz   = (const float*)d_in[8];
    const float* bz   = (const float*)d_in[9];
    const float* Wo   = (const float*)d_in[10];
    const float* bo   = (const float*)d_in[11];
    float* out = (float*)d_out;

    embed_kernel<<<BB * SS / 4, 256>>>(seqs, emb);

    for (int m = 0; m < 2; m++) {
        size_t wofs = (size_t)m * HH * HD * EE;   // 65536
        proj_kernel<0><<<dim3(128, 4), 256>>>(Wq + wofs, bq + m * 256, 0);
        proj_kernel<0><<<dim3(128, 4), 256>>>(Wk + wofs, bk + m * 256, 1);
        proj_kernel<0><<<dim3(128, 4), 256>>>(Wv + wofs, bv + m * 256, 2);
        qk_kernel<<<dim3(16, 16, 32), 256>>>();
        colstats1_kernel<<<dim3(8, 32, 4), 256>>>();
        colstats2_kernel<<<dim3(8, 32), 256>>>();
        rownorm_kernel<<<dim3(2048, 32), 256>>>();
        av_kernel<<<dim3(16, 32), 256>>>();
        proj_kernel<1><<<dim3(128, 4), 256>>>(Wz + (size_t)m * EE * (HH * HD), bz + m * EE, 0);
    }

    outpartial_kernel<<<dim3(8, BB * LB), 256>>>(Wo);
    outfinal_kernel<<<1, BB * LB>>>(bo, out);
}

// round 6
// speedup vs baseline: 2.3782x; 2.3782x over previous
#include <cuda_runtime.h>
#include <cuda_bf16.h>
#include <cstdint>

#define BB   8
#define SS   2048
#define EE   256
#define HH   4
#define HD   64
#define BHN  (BB*HH)           // 32
#define LB   16
#define XSZ  (BB*SS*EE)        // 4,194,304
#define QSZ  (BHN*SS*HD)       // 4,194,304

// ---------------- scratch (static device globals; no allocation) ----------------
__device__ __align__(16) float          g_X[XSZ];                     // residual stream fp32
__device__ __align__(16) __nv_bfloat16  g_Qh[QSZ];                    // Q bf16 [bh][s][d]
__device__ __align__(16) __nv_bfloat16  g_Kh[QSZ];                    // K bf16 [bh][t][d]
__device__ __align__(16) __nv_bfloat16  g_Vt[QSZ];                    // V bf16 transposed [bh][d][t]
__device__ __align__(16) __nv_bfloat16  g_S[(size_t)BHN*SS*SS];       // 256 MB scores -> A2 (in place)
__device__ __align__(16) float          g_psum[4*BHN*SS];
__device__ __align__(16) float          g_rcs[BHN*SS];
__device__ __align__(16) float          g_Z[XSZ];                     // Zall fp32 [b][s][h*64+d]
__device__ __align__(16) float          g_part[BB*LB*8];

// ---------------- helpers ----------------
__device__ __forceinline__ uint32_t smem_u32(const void* p) {
    uint32_t a;
    asm("{ .reg .u64 t; cvta.to.shared.u64 t, %1; cvt.u32.u64 %0, t; }" : "=r"(a) : "l"(p));
    return a;
}

__device__ __forceinline__ void ldsm_x4(uint32_t& r0, uint32_t& r1, uint32_t& r2, uint32_t& r3,
                                        uint32_t addr) {
    asm volatile("ldmatrix.sync.aligned.m8n8.x4.shared.b16 {%0,%1,%2,%3}, [%4];"
                 : "=r"(r0), "=r"(r1), "=r"(r2), "=r"(r3) : "r"(addr));
}
__device__ __forceinline__ void ldsm_x2(uint32_t& r0, uint32_t& r1, uint32_t addr) {
    asm volatile("ldmatrix.sync.aligned.m8n8.x2.shared.b16 {%0,%1}, [%2];"
                 : "=r"(r0), "=r"(r1) : "r"(addr));
}
__device__ __forceinline__ void mma16816(float* c, const uint32_t* a, const uint32_t* b) {
    asm volatile("mma.sync.aligned.m16n8k16.row.col.f32.bf16.bf16.f32 "
                 "{%0,%1,%2,%3}, {%4,%5,%6,%7}, {%8,%9}, {%0,%1,%2,%3};"
                 : "+f"(c[0]), "+f"(c[1]), "+f"(c[2]), "+f"(c[3])
                 : "r"(a[0]), "r"(a[1]), "r"(a[2]), "r"(a[3]), "r"(b[0]), "r"(b[1]));
}

// ---------------- FFMA-only exp (MUFU rt=8 would bottleneck) ----------------
__device__ __forceinline__ float fexp(float x) {
    x = fmaxf(fminf(x, 87.0f), -87.0f);
    float z = x * 1.4426950408889634f;
    int   n = __float2int_rn(z);
    float f = z - (float)n;
    float t = f * 0.6931471805599453f;
    float p = 1.98412698412e-4f;
    p = fmaf(p, t, 1.38888888889e-3f);
    p = fmaf(p, t, 8.33333333333e-3f);
    p = fmaf(p, t, 4.16666666667e-2f);
    p = fmaf(p, t, 1.66666666667e-1f);
    p = fmaf(p, t, 0.5f);
    p = fmaf(p, t, 1.0f);
    p = fmaf(p, t, 1.0f);
    return p * __int_as_float((n + 127) << 23);
}

// ---------------- embedding gather ----------------
__global__ void embed_kernel(const int* __restrict__ seqs, const float* __restrict__ emb) {
    int bs   = blockIdx.x * 4 + (threadIdx.x >> 6);
    int lane = threadIdx.x & 63;
    int tok  = seqs[bs];
    reinterpret_cast<float4*>(g_X)[(size_t)bs * 64 + lane] =
        reinterpret_cast<const float4*>(emb)[(size_t)tok * 64 + lane];
}

// ---------------- projection GEMM: C[m,n] = sum_k A[m,k]*W[n,k] (fp32 SIMT) ------------
// MODE 0: A=g_X; relu(+bias); write bf16 to Q/K [bh][s][d] or V transposed [bh][d][t]
// MODE 1: A=g_Z; += bias + residual into g_X (fp32)
template<int MODE>
__global__ void __launch_bounds__(256)
proj_kernel(const float* __restrict__ W, const float* __restrict__ bias, int osel) {
    __shared__ float As[32][132];
    __shared__ float Bs[32][68];
    int tid = threadIdx.x;
    int tx = tid & 15, ty = tid >> 4;
    int m0 = blockIdx.x * 128, n0 = blockIdx.y * 64;
    const float* A = (MODE == 0) ? g_X : g_Z;

    float acc[8][4] = {};
    for (int kc = 0; kc < 256; kc += 32) {
        #pragma unroll
        for (int i = 0; i < 4; i++) {
            int idx = tid + i * 256;
            int row = idx >> 3, c4 = (idx & 7) * 4;
            float4 a = *reinterpret_cast<const float4*>(A + (size_t)(m0 + row) * 256 + kc + c4);
            As[c4 + 0][row] = a.x; As[c4 + 1][row] = a.y;
            As[c4 + 2][row] = a.z; As[c4 + 3][row] = a.w;
        }
        #pragma unroll
        for (int i = 0; i < 2; i++) {
            int idx = tid + i * 256;
            int row = idx >> 3, c4 = (idx & 7) * 4;
            float4 w = *reinterpret_cast<const float4*>(W + (size_t)(n0 + row) * 256 + kc + c4);
            Bs[c4 + 0][row] = w.x; Bs[c4 + 1][row] = w.y;
            Bs[c4 + 2][row] = w.z; Bs[c4 + 3][row] = w.w;
        }
        __syncthreads();
        #pragma unroll 8
        for (int kk = 0; kk < 32; kk++) {
            float4 a0 = *reinterpret_cast<float4*>(&As[kk][ty * 8]);
            float4 a1 = *reinterpret_cast<float4*>(&As[kk][ty * 8 + 4]);
            float4 b  = *reinterpret_cast<float4*>(&Bs[kk][tx * 4]);
            float av[8] = {a0.x, a0.y, a0.z, a0.w, a1.x, a1.y, a1.z, a1.w};
            float bv[4] = {b.x, b.y, b.z, b.w};
            #pragma unroll
            for (int i = 0; i < 8; i++)
                #pragma unroll
                for (int j = 0; j < 4; j++)
                    acc[i][j] = fmaf(av[i], bv[j], acc[i][j]);
        }
        __syncthreads();
    }

    float4 bb = *reinterpret_cast<const float4*>(bias + n0 + tx * 4);
    if (MODE == 0) {
        int h = blockIdx.y;
        #pragma unroll
        for (int i = 0; i < 8; i++) {
            int m = m0 + ty * 8 + i;
            int b = m >> 11, s = m & 2047;
            int bh = b * HH + h;
            float v0 = fmaxf(acc[i][0] + bb.x, 0.f);
            float v1 = fmaxf(acc[i][1] + bb.y, 0.f);
            float v2 = fmaxf(acc[i][2] + bb.z, 0.f);
            float v3 = fmaxf(acc[i][3] + bb.w, 0.f);
            if (osel == 2) {
                int d = tx * 4;
                g_Vt[((size_t)bh * HD + d + 0) * SS + s] = __float2bfloat16(v0);
                g_Vt[((size_t)bh * HD + d + 1) * SS + s] = __float2bfloat16(v1);
                g_Vt[((size_t)bh * HD + d + 2) * SS + s] = __float2bfloat16(v2);
                g_Vt[((size_t)bh * HD + d + 3) * SS + s] = __float2bfloat16(v3);
            } else {
                __nv_bfloat16* outp = (osel == 0) ? g_Qh : g_Kh;
                __nv_bfloat162* dst =
                    reinterpret_cast<__nv_bfloat162*>(outp + ((size_t)bh * SS + s) * HD + tx * 4);
                dst[0] = __floats2bfloat162_rn(v0, v1);
                dst[1] = __floats2bfloat162_rn(v2, v3);
            }
        }
    } else {
        #pragma unroll
        for (int i = 0; i < 8; i++) {
            int m = m0 + ty * 8 + i;
            float* dst = &g_X[(size_t)m * 256 + n0 + tx * 4];
            float4 o = *reinterpret_cast<float4*>(dst);
            o.x += acc[i][0] + bb.x; o.y += acc[i][1] + bb.y;
            o.z += acc[i][2] + bb.z; o.w += acc[i][3] + bb.w;
            *reinterpret_cast<float4*>(dst) = o;
        }
    }
}

// ---------------- QK^T via mma.sync: per block (bh, 128s, 128t) ----------------
// smem: Qs[128][72] bf16 + Ks[128][72] bf16 (36.8KB); reused as bf16 stage [128][136].
__global__ void __launch_bounds__(256)
qk_mma_kernel() {
    __shared__ __align__(16) __nv_bfloat16 sm[2 * 128 * 72];
    __nv_bfloat16* Qs = sm;
    __nv_bfloat16* Ks = sm + 128 * 72;
    int tid = threadIdx.x, lane = tid & 31, wid = tid >> 5;
    int s0 = blockIdx.x * 128, t0 = blockIdx.y * 128, bh = blockIdx.z;

    #pragma unroll
    for (int i = 0; i < 4; i++) {
        int c = tid + i * 256;
        int r = c >> 3, o = c & 7;
        *reinterpret_cast<uint4*>(Qs + r * 72 + o * 8) =
            *reinterpret_cast<const uint4*>(g_Qh + ((size_t)bh * SS + s0 + r) * HD + o * 8);
        *reinterpret_cast<uint4*>(Ks + r * 72 + o * 8) =
            *reinterpret_cast<const uint4*>(g_Kh + ((size_t)bh * SS + t0 + r) * HD + o * 8);
    }
    __syncthreads();

    int wm = (wid & 3) * 32, wn = (wid >> 2) * 64;
    uint32_t qbase = smem_u32(Qs), kbase = smem_u32(Ks);
    float acc[2][8][4] = {};

    #pragma unroll
    for (int kk = 0; kk < 4; kk++) {
        int k0 = kk * 16;
        uint32_t a[2][4], b[8][2];
        #pragma unroll
        for (int mi = 0; mi < 2; mi++) {
            uint32_t addr = qbase +
                ((wm + mi * 16 + (lane & 15)) * 72 + k0 + (lane >> 4) * 8) * 2;
            ldsm_x4(a[mi][0], a[mi][1], a[mi][2], a[mi][3], addr);
        }
        #pragma unroll
        for (int ni = 0; ni < 8; ni++) {
            uint32_t addr = kbase +
                ((wn + ni * 8 + (lane & 7)) * 72 + k0 + ((lane >> 3) & 1) * 8) * 2;
            ldsm_x2(b[ni][0], b[ni][1], addr);
        }
        #pragma unroll
        for (int mi = 0; mi < 2; mi++)
            #pragma unroll
            for (int ni = 0; ni < 8; ni++)
                mma16816(acc[mi][ni], a[mi], b[ni]);
    }
    __syncthreads();

    // stage bf16 results (rows stride 136 bf16 = 68 words: conflict-free), then coalesced out
    __nv_bfloat16* Ss = sm;
    const float sc = 0.0625f;   // 1/sqrt(EMBED)
    #pragma unroll
    for (int mi = 0; mi < 2; mi++)
        #pragma unroll
        for (int ni = 0; ni < 8; ni++) {
            int r0 = wm + mi * 16 + (lane >> 2);
            int c  = wn + ni * 8 + (lane & 3) * 2;
            *reinterpret_cast<__nv_bfloat162*>(Ss + r0 * 136 + c) =
                __floats2bfloat162_rn(acc[mi][ni][0] * sc, acc[mi][ni][1] * sc);
            *reinterpret_cast<__nv_bfloat162*>(Ss + (r0 + 8) * 136 + c) =
                __floats2bfloat162_rn(acc[mi][ni][2] * sc, acc[mi][ni][3] * sc);
        }
    __syncthreads();
    #pragma unroll
    for (int i = 0; i < 8; i++) {
        int c = tid + i * 256;     // 2048 uint4 = 128 rows x 16
        int r = c >> 4, o = c & 15;
        *reinterpret_cast<uint4*>(g_S + ((size_t)bh * SS + s0 + r) * SS + t0 + o * 8) =
            *reinterpret_cast<uint4*>(Ss + r * 136 + o * 8);
    }
}

// ---------------- column exp-sums (softmax over query axis; scores tiny -> no max) ----------
__global__ void __launch_bounds__(256)
colsum_kernel() {
    int bh = blockIdx.y, seg = blockIdx.z;
    int tc = blockIdx.x * 256 + threadIdx.x;     // column pair index
    const __nv_bfloat162* p = reinterpret_cast<const __nv_bfloat162*>(
        g_S + (size_t)bh * SS * SS + (size_t)seg * 512 * SS) + tc;
    float s0 = 0.f, s1 = 0.f;
    #pragma unroll 8
    for (int i = 0; i < 512; i++) {
        __nv_bfloat162 v = p[(size_t)i * (SS / 2)];
        s0 += fexp(__bfloat162float(v.x));
        s1 += fexp(__bfloat162float(v.y));
    }
    int t = tc * 2;
    g_psum[(size_t)(seg * BHN + bh) * SS + t]     = s0;
    g_psum[(size_t)(seg * BHN + bh) * SS + t + 1] = s1;
}

__global__ void recip_kernel() {
    int i = blockIdx.x * 256 + threadIdx.x;
    float s = g_psum[i] + g_psum[BHN * SS + i] + g_psum[2 * BHN * SS + i] + g_psum[3 * BHN * SS + i];
    g_rcs[i] = 1.0f / s;
}

// ---------------- rowsum: A2 = exp(exp(S)*rcs[t]) / rowsum, written bf16 IN PLACE ----------
__global__ void __launch_bounds__(256)
rowsum_kernel() {
    int bh = blockIdx.y, s = blockIdx.x;
    __nv_bfloat16* row = g_S + ((size_t)bh * SS + s) * SS;
    int t0 = threadIdx.x * 8;

    uint4 raw = *reinterpret_cast<uint4*>(row + t0);
    float4 rc0 = *reinterpret_cast<const float4*>(g_rcs + bh * SS + t0);
    float4 rc1 = *reinterpret_cast<const float4*>(g_rcs + bh * SS + t0 + 4);
    __nv_bfloat162 b0 = *reinterpret_cast<__nv_bfloat162*>(&raw.x);
    __nv_bfloat162 b1 = *reinterpret_cast<__nv_bfloat162*>(&raw.y);
    __nv_bfloat162 b2 = *reinterpret_cast<__nv_bfloat162*>(&raw.z);
    __nv_bfloat162 b3 = *reinterpret_cast<__nv_bfloat162*>(&raw.w);

    float F[8];
    F[0] = fexp(fexp(__bfloat162float(b0.x)) * rc0.x);
    F[1] = fexp(fexp(__bfloat162float(b0.y)) * rc0.y);
    F[2] = fexp(fexp(__bfloat162float(b1.x)) * rc0.z);
    F[3] = fexp(fexp(__bfloat162float(b1.y)) * rc0.w);
    F[4] = fexp(fexp(__bfloat162float(b2.x)) * rc1.x);
    F[5] = fexp(fexp(__bfloat162float(b2.y)) * rc1.y);
    F[6] = fexp(fexp(__bfloat162float(b3.x)) * rc1.z);
    F[7] = fexp(fexp(__bfloat162float(b3.y)) * rc1.w);

    float loc = ((F[0] + F[1]) + (F[2] + F[3])) + ((F[4] + F[5]) + (F[6] + F[7]));
    #pragma unroll
    for (int o = 16; o; o >>= 1) loc += __shfl_xor_sync(0xffffffffu, loc, o);
    __shared__ float red[9];
    if ((threadIdx.x & 31) == 0) red[threadIdx.x >> 5] = loc;
    __syncthreads();
    if (threadIdx.x == 0) {
        float tt = ((red[0] + red[1]) + (red[2] + red[3])) + ((red[4] + red[5]) + (red[6] + red[7]));
        red[8] = 1.0f / tt;
    }
    __syncthreads();
    float r = red[8];

    __nv_bfloat162 o0 = __floats2bfloat162_rn(F[0] * r, F[1] * r);
    __nv_bfloat162 o1 = __floats2bfloat162_rn(F[2] * r, F[3] * r);
    __nv_bfloat162 o2 = __floats2bfloat162_rn(F[4] * r, F[5] * r);
    __nv_bfloat162 o3 = __floats2bfloat162_rn(F[6] * r, F[7] * r);
    raw.x = *reinterpret_cast<uint32_t*>(&o0);
    raw.y = *reinterpret_cast<uint32_t*>(&o1);
    raw.z = *reinterpret_cast<uint32_t*>(&o2);
    raw.w = *reinterpret_cast<uint32_t*>(&o3);
    *reinterpret_cast<uint4*>(row + t0) = raw;
}

// ---------------- Z = A2 @ V via mma.sync: per block (bh, 128 s-rows), K=2048 chunks of 64 ---
__global__ void __launch_bounds__(256)
av_mma_kernel() {
    __shared__ __align__(16) __nv_bfloat16 As[128 * 72];
    __shared__ __align__(16) __nv_bfloat16 Vs[64 * 72];
    int tid = threadIdx.x, lane = tid & 31, wid = tid >> 5;
    int s0 = blockIdx.x * 128, bh = blockIdx.y;
    int wm = (wid & 3) * 32, wn = (wid >> 2) * 32;
    uint32_t abase = smem_u32(As), vbase = smem_u32(Vs);

    float acc[2][4][4] = {};

    // prefetch chunk 0
    uint4 pa[4], pv[2];
    {
        #pragma unroll
        for (int i = 0; i < 4; i++) {
            int c = tid + i * 256;
            int r = c >> 3, o = c & 7;
            pa[i] = *reinterpret_cast<const uint4*>(g_S + ((size_t)bh * SS + s0 + r) * SS + o * 8);
        }
        #pragma unroll
        for (int i = 0; i < 2; i++) {
            int c = tid + i * 256;
            int r = c >> 3, o = c & 7;
            pv[i] = *reinterpret_cast<const uint4*>(g_Vt + ((size_t)bh * HD + r) * SS + o * 8);
        }
    }

    for (int tc = 0; tc < 32; tc++) {
        #pragma unroll
        for (int i = 0; i < 4; i++) {
            int c = tid + i * 256;
            int r = c >> 3, o = c & 7;
            *reinterpret_cast<uint4*>(As + r * 72 + o * 8) = pa[i];
        }
        #pragma unroll
        for (int i = 0; i < 2; i++) {
            int c = tid + i * 256;
            int r = c >> 3, o = c & 7;
            *reinterpret_cast<uint4*>(Vs + r * 72 + o * 8) = pv[i];
        }
        __syncthreads();

        if (tc < 31) {
            int t1 = (tc + 1) * 64;
            #pragma unroll
            for (int i = 0; i < 4; i++) {
                int c = tid + i * 256;
                int r = c >> 3, o = c & 7;
                pa[i] = *reinterpret_cast<const uint4*>(
                    g_S + ((size_t)bh * SS + s0 + r) * SS + t1 + o * 8);
            }
            #pragma unroll
            for (int i = 0; i < 2; i++) {
                int c = tid + i * 256;
                int r = c >> 3, o = c & 7;
                pv[i] = *reinterpret_cast<const uint4*>(
                    g_Vt + ((size_t)bh * HD + r) * SS + t1 + o * 8);
            }
        }

        #pragma unroll
        for (int kk = 0; kk < 4; kk++) {
            int k0 = kk * 16;
            uint32_t a[2][4], b[4][2];
            #pragma unroll
            for (int mi = 0; mi < 2; mi++) {
                uint32_t addr = abase +
                    ((wm + mi * 16 + (lane & 15)) * 72 + k0 + (lane >> 4) * 8) * 2;
                ldsm_x4(a[mi][0], a[mi][1], a[mi][2], a[mi][3], addr);
            }
            #pragma unroll
            for (int ni = 0; ni < 4; ni++) {
                uint32_t addr = vbase +
                    ((wn + ni * 8 + (lane & 7)) * 72 + k0 + ((lane >> 3) & 1) * 8) * 2;
                ldsm_x2(b[ni][0], b[ni][1], addr);
            }
            #pragma unroll
            for (int mi = 0; mi < 2; mi++)
                #pragma unroll
                for (int ni = 0; ni < 4; ni++)
                    mma16816(acc[mi][ni], a[mi], b[ni]);
        }
        __syncthreads();
    }

    int b = bh >> 2, h = bh & 3;
    #pragma unroll
    for (int mi = 0; mi < 2; mi++)
        #pragma unroll
        for (int ni = 0; ni < 4; ni++) {
            int r = s0 + wm + mi * 16 + (lane >> 2);
            int c = h * HD + wn + ni * 8 + (lane & 3) * 2;
            float2 v0 = make_float2(acc[mi][ni][0], acc[mi][ni][1]);
            float2 v1 = make_float2(acc[mi][ni][2], acc[mi][ni][3]);
            *reinterpret_cast<float2*>(&g_Z[((size_t)(b * SS) + r) * EE + c]) = v0;
            *reinterpret_cast<float2*>(&g_Z[((size_t)(b * SS) + r + 8) * EE + c]) = v1;
        }
}

// ---------------- final classifier ----------------
__global__ void __launch_bounds__(256)
outpartial_kernel(const float* __restrict__ Wo) {
    int bl = blockIdx.y;
    int sp = blockIdx.x;
    int l = bl & 15, b = bl >> 4;
    const float4* wp = reinterpret_cast<const float4*>(Wo + (size_t)l * (SS * EE)) + (size_t)sp * 16384;
    const float4* xp = reinterpret_cast<const float4*>(g_X + (size_t)b * (SS * EE)) + (size_t)sp * 16384;
    float s = 0.f;
    #pragma unroll 4
    for (int i = 0; i < 64; i++) {
        int idx = threadIdx.x + i * 256;
        float4 w = wp[idx], x = xp[idx];
        s = fmaf(w.x, x.x, fmaf(w.y, x.y, fmaf(w.z, x.z, fmaf(w.w, x.w, s))));
    }
    #pragma unroll
    for (int o = 16; o; o >>= 1) s += __shfl_xor_sync(0xffffffffu, s, o);
    __shared__ float red[8];
    if ((threadIdx.x & 31) == 0) red[threadIdx.x >> 5] = s;
    __syncthreads();
    if (threadIdx.x == 0) {
        float tt = ((red[0] + red[1]) + (red[2] + red[3])) + ((red[4] + red[5]) + (red[6] + red[7]));
        g_part[bl * 8 + sp] = tt;
    }
}

__global__ void outfinal_kernel(const float* __restrict__ bo, float* __restrict__ out) {
    int bl = threadIdx.x;
    float s = bo[bl & 15];
    #pragma unroll
    for (int i = 0; i < 8; i++) s += g_part[bl * 8 + i];
    out[bl] = 1.0f / (1.0f + fexp(-s));
}

// ---------------- launch ----------------
extern "C" void kernel_launch(void* const* d_in, const int* in_sizes, int n_in,
                              void* d_out, int out_size) {
    const int*   seqs = (const int*)  d_in[0];
    const float* emb  = (const float*)d_in[1];
    const float* Wq   = (const float*)d_in[2];
    const float* bq   = (const float*)d_in[3];
    const float* Wk   = (const float*)d_in[4];
    const float* bk   = (const float*)d_in[5];
    const float* Wv   = (const float*)d_in[6];
    const float* bv   = (const float*)d_in[7];
    const float* Wz   = (const float*)d_in[8];
    const float* bz   = (const float*)d_in[9];
    const float* Wo   = (const float*)d_in[10];
    const float* bo   = (const float*)d_in[11];
    float* out = (float*)d_out;

    embed_kernel<<<BB * SS / 4, 256>>>(seqs, emb);

    for (int m = 0; m < 2; m++) {
        size_t wofs = (size_t)m * HH * HD * EE;
        proj_kernel<0><<<dim3(128, 4), 256>>>(Wq + wofs, bq + m * 256, 0);
        proj_kernel<0><<<dim3(128, 4), 256>>>(Wk + wofs, bk + m * 256, 1);
        proj_kernel<0><<<dim3(128, 4), 256>>>(Wv + wofs, bv + m * 256, 2);
        qk_mma_kernel<<<dim3(16, 16, 32), 256>>>();
        colsum_kernel<<<dim3(4, 32, 4), 256>>>();
        recip_kernel<<<256, 256>>>();
        rowsum_kernel<<<dim3(2048, 32), 256>>>();
        av_mma_kernel<<<dim3(16, 32), 256>>>();
        proj_kernel<1><<<dim3(128, 4), 256>>>(Wz + (size_t)m * EE * (HH * HD), bz + m * EE, 0);
    }

    outpartial_kernel<<<dim3(8, BB * LB), 256>>>(Wo);
    outfinal_kernel<<<1, BB * LB>>>(bo, out);
}